// round 7
// baseline (speedup 1.0000x reference)
#include <cuda_runtime.h>
#include <cuda_fp16.h>
#include <cstdint>

// Causal SDPA: B=2, H=16, S=2048, D=128, fp32 in/out.
// R7: all smem fragment loads via ldmatrix.m8n8.x4 (K/V b-frags, P a-frags):
//     272 scalar LDS -> 68 LDSM per warp-tile. Same math as R6:
//     fp16 mma.sync.m16n8k16 w/ f32 accum, flash attention, online softmax,
//     cp.async double buffering, prologue K->fp16 + V->fp16-transposed.

#define B_ 2
#define H_ 16
#define S_ 2048
#define D_ 128

constexpr int BR      = 128;
constexpr int BC      = 64;
constexpr int THREADS = 256;

// smem row strides in 32-bit words; stride % 32 == 4 so each ldmatrix
// 8-row phase covers all 32 banks (conflict-free).
constexpr int KSTW = 68;   // K tile row: 128 halfs (64 w) + 4 pad
constexpr int VSTW = 36;   // VT tile row: 64 halfs (32 w) + 4 pad
constexpr int PSTW = 36;   // P tile row:  64 halfs (32 w) + 4 pad

constexpr int KTILE_W = BC * KSTW;    // 4352 words / stage
constexpr int VTILE_W = D_ * VSTW;    // 4608 words / stage (VT has D_ rows)
constexpr int PTILE_W = BR * PSTW;    // 4608 words
constexpr int SMEM_WORDS = 2 * KTILE_W + 2 * VTILE_W + PTILE_W;  // 22528
constexpr int SMEM_BYTES = SMEM_WORDS * 4;                        // 90112 B

constexpr int KV_ELEMS = B_ * H_ * S_ * D_;   // 8,388,608 per tensor

// fp16 scratch (static device arrays: allocation-free). 16MB each.
__device__ __align__(16) __half g_kth[KV_ELEMS];
__device__ __align__(16) __half g_vth[KV_ELEMS];   // per-head transposed: [bh][d][s]

// ---------------------------------------------------------------------------
// Prologue 1: K -> fp16, same layout.
// ---------------------------------------------------------------------------
__global__ void __launch_bounds__(256)
cvt_k_kernel(const float4* __restrict__ k) {
    const int n = KV_ELEMS / 4;
    uint2* kd = reinterpret_cast<uint2*>(g_kth);
    for (int i = blockIdx.x * blockDim.x + threadIdx.x; i < n;
         i += gridDim.x * blockDim.x) {
        float4 a = k[i];
        __half2 lo = __floats2half2_rn(a.x, a.y);
        __half2 hi = __floats2half2_rn(a.z, a.w);
        uint2 o;
        o.x = *(uint32_t*)&lo;
        o.y = *(uint32_t*)&hi;
        kd[i] = o;
    }
}

// ---------------------------------------------------------------------------
// Prologue 2: V -> fp16 transposed per (b,h): VT[d][s] = V[s][d].
// 64x64 tiles: float4 coalesced loads, half2 coalesced stores (128B rows).
// ---------------------------------------------------------------------------
__global__ void __launch_bounds__(256)
transpose_v_kernel(const float* __restrict__ v) {
    __shared__ __half tile[64][65];
    const int bh = blockIdx.z;
    const int s0 = blockIdx.x * 64;
    const int d0 = blockIdx.y * 64;
    const float* vp = v + (long)bh * S_ * D_;
    __half* vtp = g_vth + (long)bh * (long)D_ * S_;

    const int tx = threadIdx.x & 15;   // float4 column within 64 floats
    const int ty = threadIdx.x >> 4;   // row 0..15
    #pragma unroll
    for (int p = 0; p < 4; ++p) {
        int si = ty + p * 16;
        float4 a = *(const float4*)(vp + (long)(s0 + si) * D_ + d0 + tx * 4);
        tile[si][tx * 4 + 0] = __float2half_rn(a.x);
        tile[si][tx * 4 + 1] = __float2half_rn(a.y);
        tile[si][tx * 4 + 2] = __float2half_rn(a.z);
        tile[si][tx * 4 + 3] = __float2half_rn(a.w);
    }
    __syncthreads();

    const int lane = threadIdx.x & 31;
    const int w    = threadIdx.x >> 5;
    #pragma unroll
    for (int p = 0; p < 8; ++p) {
        int di = w + p * 8;
        __half2 h = __halves2half2(tile[2 * lane][di], tile[2 * lane + 1][di]);
        *(__half2*)(vtp + (long)(d0 + di) * S_ + s0 + 2 * lane) = h;
    }
}

// ---------------------------------------------------------------------------
// Main flash-attention kernel
// ---------------------------------------------------------------------------
__device__ __forceinline__ void mma_f16(float c[4],
                                        uint32_t a0, uint32_t a1, uint32_t a2, uint32_t a3,
                                        uint32_t b0, uint32_t b1) {
    asm volatile(
        "mma.sync.aligned.m16n8k16.row.col.f32.f16.f16.f32 "
        "{%0,%1,%2,%3}, {%4,%5,%6,%7}, {%8,%9}, {%0,%1,%2,%3};"
        : "+f"(c[0]), "+f"(c[1]), "+f"(c[2]), "+f"(c[3])
        : "r"(a0), "r"(a1), "r"(a2), "r"(a3), "r"(b0), "r"(b1));
}

__device__ __forceinline__ void ldsm4(uint32_t& r0, uint32_t& r1,
                                      uint32_t& r2, uint32_t& r3, uint32_t addr) {
    asm volatile("ldmatrix.sync.aligned.m8n8.x4.shared.b16 {%0,%1,%2,%3}, [%4];"
                 : "=r"(r0), "=r"(r1), "=r"(r2), "=r"(r3) : "r"(addr));
}

__device__ __forceinline__ void cp_async16(uint32_t dst_smem, const void* src) {
    asm volatile("cp.async.cg.shared.global [%0], [%1], 16;" :: "r"(dst_smem), "l"(src));
}

__device__ __forceinline__ uint32_t pack2(float a, float b) {
    __half2 h = __floats2half2_rn(a, b);
    return *(uint32_t*)&h;
}

// Load one K tile (BC rows x 128 halfs) + one VT tile (128 rows x BC halfs).
__device__ __forceinline__ void load_kv_tile(const __half* kg, const __half* vtg,
                                             uint32_t kdst, uint32_t vdst, int tid) {
    #pragma unroll
    for (int it = 0; it < (BC * 16) / THREADS; ++it) {
        int i = tid + it * THREADS;
        int row = i >> 4, ch = i & 15;
        cp_async16(kdst + (uint32_t)(row * KSTW + ch * 4) * 4u, kg + row * D_ + ch * 8);
    }
    #pragma unroll
    for (int it = 0; it < (D_ * 8) / THREADS; ++it) {
        int i = tid + it * THREADS;
        int row = i >> 3, ch = i & 7;
        cp_async16(vdst + (uint32_t)(row * VSTW + ch * 4) * 4u, vtg + (long)row * S_ + ch * 8);
    }
    asm volatile("cp.async.commit_group;");
}

__global__ __launch_bounds__(THREADS, 1)
void fa_causal_f16_kernel(const float* __restrict__ q, float* __restrict__ out) {
    extern __shared__ __align__(16) uint32_t smem[];
    uint32_t* psm = smem + 2 * KTILE_W + 2 * VTILE_W;       // [BR][PSTW]

    const int tid  = threadIdx.x;
    const int w    = tid >> 5;
    const int lane = tid & 31;
    const int g    = lane >> 2;   // group id (rows g, g+8 of mma tile)
    const int c    = lane & 3;    // thread-in-group

    // ldmatrix per-lane row/selector decomposition
    const int r8 = lane & 7;            // row within 8x8 matrix
    const int s3 = (lane >> 3) & 1;     // chunk select (+4 words)
    const int s4 = lane >> 4;           // second-k-step select (+8 words)

    // longest-running q-tiles launch first
    const int qt     = (int)(gridDim.x - 1) - (int)blockIdx.x;
    const int bh     = blockIdx.y;
    const long base  = (long)bh * S_ * D_;
    const int q_base = qt * BR;
    const int njt    = (q_base + BR) / BC;   // number of causal kv tiles
    const int wrow   = q_base + w * 16;      // this warp's first q row

    const float scale = 0.08838834764831845f;   // D^-0.5

    const uint32_t smem_u32 = (uint32_t)__cvta_generic_to_shared(smem);
    const uint32_t k_u32    = smem_u32;
    const uint32_t v_u32    = smem_u32 + (uint32_t)(2 * KTILE_W) * 4u;
    const uint32_t p_u32    = smem_u32 + (uint32_t)(2 * KTILE_W + 2 * VTILE_W) * 4u;

    // per-lane ldmatrix byte offsets within a tile
    const uint32_t koff = (uint32_t)(r8 * KSTW + s4 * 8 + s3 * 4) * 4u;
    const uint32_t voff = (uint32_t)(r8 * VSTW + s4 * 8 + s3 * 4) * 4u;
    const uint32_t poff = (uint32_t)((w * 16 + r8 + s3 * 8) * PSTW + s4 * 4) * 4u;

    const __half* kg  = g_kth + base;            // [s][d]
    const __half* vtg = g_vth + base;            // [d][s]

    // ---- start loading tile 0 ----
    load_kv_tile(kg, vtg, k_u32, v_u32, tid);

    // ---- Q: load, scale, pack to half2 a-frags (8 k-steps x 4 frags) ----
    uint32_t qreg[8][4];
    {
        const float* qp = q + base;
        const long r0 = wrow + g, r1 = r0 + 8;
        #pragma unroll
        for (int ks = 0; ks < 8; ++ks) {
            int col = ks * 16 + 2 * c;
            qreg[ks][0] = pack2(qp[r0 * D_ + col]     * scale, qp[r0 * D_ + col + 1] * scale);
            qreg[ks][1] = pack2(qp[r1 * D_ + col]     * scale, qp[r1 * D_ + col + 1] * scale);
            qreg[ks][2] = pack2(qp[r0 * D_ + col + 8] * scale, qp[r0 * D_ + col + 9] * scale);
            qreg[ks][3] = pack2(qp[r1 * D_ + col + 8] * scale, qp[r1 * D_ + col + 9] * scale);
        }
    }

    float oacc[16][4];
    #pragma unroll
    for (int nt = 0; nt < 16; ++nt)
        oacc[nt][0] = oacc[nt][1] = oacc[nt][2] = oacc[nt][3] = 0.f;
    float m0 = -1e30f, m1 = -1e30f, l0 = 0.f, l1 = 0.f;

    for (int j = 0; j < njt; ++j) {
        const int st = j & 1;
        if (j + 1 < njt) {
            const int ns = (j + 1) & 1;
            load_kv_tile(kg + (long)(j + 1) * BC * D_,
                         vtg + (j + 1) * BC,     // VT: advance along s (columns)
                         k_u32 + (uint32_t)(ns * KTILE_W) * 4u,
                         v_u32 + (uint32_t)(ns * VTILE_W) * 4u, tid);
            asm volatile("cp.async.wait_group 1;");
        } else {
            asm volatile("cp.async.wait_group 0;");
        }
        __syncthreads();

        const int kvb = j * BC;

        // Skip warp-tiles entirely above the diagonal (fully masked).
        if (wrow + 15 >= kvb) {
            const uint32_t ktb = k_u32 + (uint32_t)(st * KTILE_W) * 4u + koff;
            const uint32_t vtb = v_u32 + (uint32_t)(st * VTILE_W) * 4u + voff;

            // ---- S = Q K^T  (16x64 per warp, 8x8 mmas) ----
            float sacc[8][4];
            #pragma unroll
            for (int nt = 0; nt < 8; ++nt)
                sacc[nt][0] = sacc[nt][1] = sacc[nt][2] = sacc[nt][3] = 0.f;

            #pragma unroll
            for (int nt = 0; nt < 8; ++nt) {
                const uint32_t krow = ktb + (uint32_t)(nt * 8 * KSTW) * 4u;
                #pragma unroll
                for (int kp = 0; kp < 4; ++kp) {
                    uint32_t b0, b1, b2, b3;
                    ldsm4(b0, b1, b2, b3, krow + (uint32_t)(kp * 16) * 4u);
                    mma_f16(sacc[nt], qreg[2*kp][0], qreg[2*kp][1], qreg[2*kp][2], qreg[2*kp][3], b0, b1);
                    mma_f16(sacc[nt], qreg[2*kp+1][0], qreg[2*kp+1][1], qreg[2*kp+1][2], qreg[2*kp+1][3], b2, b3);
                }
            }

            // ---- causal mask (near-diagonal tiles only) ----
            if (kvb + BC - 1 > wrow) {
                #pragma unroll
                for (int nt = 0; nt < 8; ++nt) {
                    #pragma unroll
                    for (int idx = 0; idx < 4; ++idx) {
                        int col = kvb + nt * 8 + (c << 1) + (idx & 1);
                        int row = wrow + g + ((idx >> 1) << 3);
                        if (col > row) sacc[nt][idx] = -1e30f;
                    }
                }
            }

            // ---- online softmax (rows g and g+8) ----
            float tm0 = -1e30f, tm1 = -1e30f;
            #pragma unroll
            for (int nt = 0; nt < 8; ++nt) {
                tm0 = fmaxf(tm0, fmaxf(sacc[nt][0], sacc[nt][1]));
                tm1 = fmaxf(tm1, fmaxf(sacc[nt][2], sacc[nt][3]));
            }
            tm0 = fmaxf(tm0, __shfl_xor_sync(0xffffffffu, tm0, 1));
            tm0 = fmaxf(tm0, __shfl_xor_sync(0xffffffffu, tm0, 2));
            tm1 = fmaxf(tm1, __shfl_xor_sync(0xffffffffu, tm1, 1));
            tm1 = fmaxf(tm1, __shfl_xor_sync(0xffffffffu, tm1, 2));

            const float nm0 = fmaxf(m0, tm0), nm1 = fmaxf(m1, tm1);
            const float a0 = __expf(m0 - nm0), a1 = __expf(m1 - nm1);
            m0 = nm0; m1 = nm1;

            float ts0 = 0.f, ts1 = 0.f;
            uint32_t* prow0 = psm + (w * 16 + g) * PSTW;
            uint32_t* prow1 = prow0 + 8 * PSTW;
            #pragma unroll
            for (int nt = 0; nt < 8; ++nt) {
                float p00 = __expf(sacc[nt][0] - nm0);
                float p01 = __expf(sacc[nt][1] - nm0);
                float p10 = __expf(sacc[nt][2] - nm1);
                float p11 = __expf(sacc[nt][3] - nm1);
                ts0 += p00 + p01;
                ts1 += p10 + p11;
                prow0[nt * 4 + c] = pack2(p00, p01);
                prow1[nt * 4 + c] = pack2(p10, p11);
            }
            ts0 += __shfl_xor_sync(0xffffffffu, ts0, 1);
            ts0 += __shfl_xor_sync(0xffffffffu, ts0, 2);
            ts1 += __shfl_xor_sync(0xffffffffu, ts1, 1);
            ts1 += __shfl_xor_sync(0xffffffffu, ts1, 2);
            l0 = l0 * a0 + ts0;
            l1 = l1 * a1 + ts1;

            #pragma unroll
            for (int nt = 0; nt < 16; ++nt) {
                oacc[nt][0] *= a0; oacc[nt][1] *= a0;
                oacc[nt][2] *= a1; oacc[nt][3] *= a1;
            }

            __syncwarp();   // P rows are warp-private; order STS before ldmatrix

            // ---- O += P V  (16x128 per warp, 4x16 mmas) ----
            uint32_t pa[4][4];
            #pragma unroll
            for (int ks = 0; ks < 4; ++ks)
                ldsm4(pa[ks][0], pa[ks][1], pa[ks][2], pa[ks][3],
                      p_u32 + poff + (uint32_t)(ks * 8) * 4u);

            #pragma unroll
            for (int nt = 0; nt < 16; ++nt) {
                const uint32_t vrow = vtb + (uint32_t)(nt * 8 * VSTW) * 4u;
                uint32_t b0, b1, b2, b3, b4, b5, b6, b7;
                ldsm4(b0, b1, b2, b3, vrow);
                ldsm4(b4, b5, b6, b7, vrow + 16u * 4u);
                mma_f16(oacc[nt], pa[0][0], pa[0][1], pa[0][2], pa[0][3], b0, b1);
                mma_f16(oacc[nt], pa[1][0], pa[1][1], pa[1][2], pa[1][3], b2, b3);
                mma_f16(oacc[nt], pa[2][0], pa[2][1], pa[2][2], pa[2][3], b4, b5);
                mma_f16(oacc[nt], pa[3][0], pa[3][1], pa[3][2], pa[3][3], b6, b7);
            }
        }

        __syncthreads();  // all warps done with this stage before refill
    }

    // ---- epilogue: normalize and store ----
    const float inv0 = 1.f / l0, inv1 = 1.f / l1;
    float* op = out + base;
    const long r0 = wrow + g, r1 = r0 + 8;
    #pragma unroll
    for (int nt = 0; nt < 16; ++nt) {
        int col = nt * 8 + (c << 1);
        float2 o0 = make_float2(oacc[nt][0] * inv0, oacc[nt][1] * inv0);
        float2 o1 = make_float2(oacc[nt][2] * inv1, oacc[nt][3] * inv1);
        *(float2*)(op + r0 * D_ + col) = o0;
        *(float2*)(op + r1 * D_ + col) = o1;
    }
}

extern "C" void kernel_launch(void* const* d_in, const int* in_sizes, int n_in,
                              void* d_out, int out_size) {
    const float* q = (const float*)d_in[0];
    const float* k = (const float*)d_in[1];
    const float* v = (const float*)d_in[2];
    float* out = (float*)d_out;

    cvt_k_kernel<<<1024, 256>>>((const float4*)k);
    dim3 tgrid(S_ / 64, D_ / 64, B_ * H_);
    transpose_v_kernel<<<tgrid, 256>>>(v);

    cudaFuncSetAttribute(fa_causal_f16_kernel,
                         cudaFuncAttributeMaxDynamicSharedMemorySize, SMEM_BYTES);
    dim3 grid(S_ / BR, B_ * H_);
    fa_causal_f16_kernel<<<grid, THREADS, SMEM_BYTES>>>(q, out);
}

// round 8
// speedup vs baseline: 1.1253x; 1.1253x over previous
#include <cuda_runtime.h>
#include <cuda_fp16.h>
#include <cstdint>

// Causal SDPA: B=2, H=16, S=2048, D=128, fp32 in/out.
// R8: BR=64 / 4-warp CTAs -> 2 independent CTAs resident per SM (occ 25%).
//     Two CTAs overlap softmax/barrier phases with MMA phases; barriers no
//     longer couple all warps on an SM. Same math as R6/R7: fp16 m16n8k16
//     mma w/ f32 accum, ldmatrix frag loads, cp.async double buffering,
//     fused prologue (K->fp16 + V->fp16-transposed).

#define B_ 2
#define H_ 16
#define S_ 2048
#define D_ 128

constexpr int BR      = 64;
constexpr int BC      = 64;
constexpr int THREADS = 128;

// smem row strides in 32-bit words; stride % 32 == 4 so each ldmatrix
// 8-row phase covers all 32 banks (conflict-free).
constexpr int KSTW = 68;   // K tile row: 128 halfs (64 w) + 4 pad
constexpr int VSTW = 36;   // VT tile row: 64 halfs (32 w) + 4 pad
constexpr int PSTW = 36;   // P tile row:  64 halfs (32 w) + 4 pad

constexpr int KTILE_W = BC * KSTW;    // 4352 words / stage
constexpr int VTILE_W = D_ * VSTW;    // 4608 words / stage (VT has D_ rows)
constexpr int PTILE_W = BR * PSTW;    // 2304 words
constexpr int SMEM_WORDS = 2 * KTILE_W + 2 * VTILE_W + PTILE_W;  // 20224
constexpr int SMEM_BYTES = SMEM_WORDS * 4;                        // 80896 B

constexpr int KV_ELEMS = B_ * H_ * S_ * D_;   // 8,388,608 per tensor

// fp16 scratch (static device arrays: allocation-free). 16MB each.
__device__ __align__(16) __half g_kth[KV_ELEMS];
__device__ __align__(16) __half g_vth[KV_ELEMS];   // per-head transposed: [bh][d][s]

// ---------------------------------------------------------------------------
// Fused prologue: each block transposes one 64x64 V tile to fp16 AND converts
// a 1024-float4 slice of K to fp16. One launch instead of two.
// grid = (S/64, D/64, B*H), 256 threads.
// ---------------------------------------------------------------------------
__global__ void __launch_bounds__(256)
prep_kv_kernel(const float* __restrict__ v, const float4* __restrict__ k) {
    __shared__ __half tile[64][65];
    const int bh = blockIdx.z;
    const int s0 = blockIdx.x * 64;
    const int d0 = blockIdx.y * 64;
    const float* vp = v + (long)bh * S_ * D_;
    __half* vtp = g_vth + (long)bh * (long)D_ * S_;

    // ---- V tile: float4 coalesced loads into smem (as fp16) ----
    const int tx = threadIdx.x & 15;
    const int ty = threadIdx.x >> 4;
    #pragma unroll
    for (int p = 0; p < 4; ++p) {
        int si = ty + p * 16;
        float4 a = *(const float4*)(vp + (long)(s0 + si) * D_ + d0 + tx * 4);
        tile[si][tx * 4 + 0] = __float2half_rn(a.x);
        tile[si][tx * 4 + 1] = __float2half_rn(a.y);
        tile[si][tx * 4 + 2] = __float2half_rn(a.z);
        tile[si][tx * 4 + 3] = __float2half_rn(a.w);
    }

    // ---- K slice: pure elementwise convert (overlaps the barrier) ----
    {
        const long nblk = (long)gridDim.x * gridDim.y * gridDim.z;
        const long bid  = (long)(blockIdx.z * gridDim.y + blockIdx.y) * gridDim.x
                        + blockIdx.x;
        const long per  = (KV_ELEMS / 4) / nblk;       // float4 per block
        uint2* kd = reinterpret_cast<uint2*>(g_kth);
        long i0 = bid * per;
        for (long i = i0 + threadIdx.x; i < i0 + per; i += 256) {
            float4 a = k[i];
            __half2 lo = __floats2half2_rn(a.x, a.y);
            __half2 hi = __floats2half2_rn(a.z, a.w);
            uint2 o;
            o.x = *(uint32_t*)&lo;
            o.y = *(uint32_t*)&hi;
            kd[i] = o;
        }
    }
    __syncthreads();

    // ---- V tile: half2 coalesced stores (128B rows) ----
    const int lane = threadIdx.x & 31;
    const int w    = threadIdx.x >> 5;
    #pragma unroll
    for (int p = 0; p < 8; ++p) {
        int di = w + p * 8;
        __half2 h = __halves2half2(tile[2 * lane][di], tile[2 * lane + 1][di]);
        *(__half2*)(vtp + (long)(d0 + di) * S_ + s0 + 2 * lane) = h;
    }
}

// ---------------------------------------------------------------------------
// Main flash-attention kernel
// ---------------------------------------------------------------------------
__device__ __forceinline__ void mma_f16(float c[4],
                                        uint32_t a0, uint32_t a1, uint32_t a2, uint32_t a3,
                                        uint32_t b0, uint32_t b1) {
    asm volatile(
        "mma.sync.aligned.m16n8k16.row.col.f32.f16.f16.f32 "
        "{%0,%1,%2,%3}, {%4,%5,%6,%7}, {%8,%9}, {%0,%1,%2,%3};"
        : "+f"(c[0]), "+f"(c[1]), "+f"(c[2]), "+f"(c[3])
        : "r"(a0), "r"(a1), "r"(a2), "r"(a3), "r"(b0), "r"(b1));
}

__device__ __forceinline__ void ldsm4(uint32_t& r0, uint32_t& r1,
                                      uint32_t& r2, uint32_t& r3, uint32_t addr) {
    asm volatile("ldmatrix.sync.aligned.m8n8.x4.shared.b16 {%0,%1,%2,%3}, [%4];"
                 : "=r"(r0), "=r"(r1), "=r"(r2), "=r"(r3) : "r"(addr));
}

__device__ __forceinline__ void cp_async16(uint32_t dst_smem, const void* src) {
    asm volatile("cp.async.cg.shared.global [%0], [%1], 16;" :: "r"(dst_smem), "l"(src));
}

__device__ __forceinline__ uint32_t pack2(float a, float b) {
    __half2 h = __floats2half2_rn(a, b);
    return *(uint32_t*)&h;
}

// Load one K tile (BC rows x 128 halfs) + one VT tile (128 rows x BC halfs).
__device__ __forceinline__ void load_kv_tile(const __half* kg, const __half* vtg,
                                             uint32_t kdst, uint32_t vdst, int tid) {
    #pragma unroll
    for (int it = 0; it < (BC * 16) / THREADS; ++it) {
        int i = tid + it * THREADS;
        int row = i >> 4, ch = i & 15;
        cp_async16(kdst + (uint32_t)(row * KSTW + ch * 4) * 4u, kg + row * D_ + ch * 8);
    }
    #pragma unroll
    for (int it = 0; it < (D_ * 8) / THREADS; ++it) {
        int i = tid + it * THREADS;
        int row = i >> 3, ch = i & 7;
        cp_async16(vdst + (uint32_t)(row * VSTW + ch * 4) * 4u, vtg + (long)row * S_ + ch * 8);
    }
    asm volatile("cp.async.commit_group;");
}

__global__ __launch_bounds__(THREADS, 2)
void fa_causal_f16_kernel(const float* __restrict__ q, float* __restrict__ out) {
    extern __shared__ __align__(16) uint32_t smem[];
    uint32_t* psm = smem + 2 * KTILE_W + 2 * VTILE_W;       // [BR][PSTW]

    const int tid  = threadIdx.x;
    const int w    = tid >> 5;
    const int lane = tid & 31;
    const int g    = lane >> 2;   // group id (rows g, g+8 of mma tile)
    const int c    = lane & 3;    // thread-in-group

    // ldmatrix per-lane row/selector decomposition
    const int r8 = lane & 7;            // row within 8x8 matrix
    const int s3 = (lane >> 3) & 1;     // chunk select (+4 words)
    const int s4 = lane >> 4;           // second-k-step select (+8 words)

    // longest-running q-tiles launch first
    const int qt     = (int)(gridDim.x - 1) - (int)blockIdx.x;
    const int bh     = blockIdx.y;
    const long base  = (long)bh * S_ * D_;
    const int q_base = qt * BR;
    const int njt    = (q_base + BR) / BC;   // number of causal kv tiles
    const int wrow   = q_base + w * 16;      // this warp's first q row

    const float scale = 0.08838834764831845f;   // D^-0.5

    const uint32_t smem_u32 = (uint32_t)__cvta_generic_to_shared(smem);
    const uint32_t k_u32    = smem_u32;
    const uint32_t v_u32    = smem_u32 + (uint32_t)(2 * KTILE_W) * 4u;
    const uint32_t p_u32    = smem_u32 + (uint32_t)(2 * KTILE_W + 2 * VTILE_W) * 4u;

    // per-lane ldmatrix byte offsets within a tile
    const uint32_t koff = (uint32_t)(r8 * KSTW + s4 * 8 + s3 * 4) * 4u;
    const uint32_t voff = (uint32_t)(r8 * VSTW + s4 * 8 + s3 * 4) * 4u;
    const uint32_t poff = (uint32_t)((w * 16 + r8 + s3 * 8) * PSTW + s4 * 4) * 4u;

    const __half* kg  = g_kth + base;            // [s][d]
    const __half* vtg = g_vth + base;            // [d][s]

    // ---- start loading tile 0 ----
    load_kv_tile(kg, vtg, k_u32, v_u32, tid);

    // ---- Q: load, scale, pack to half2 a-frags (8 k-steps x 4 frags) ----
    uint32_t qreg[8][4];
    {
        const float* qp = q + base;
        const long r0 = wrow + g, r1 = r0 + 8;
        #pragma unroll
        for (int ks = 0; ks < 8; ++ks) {
            int col = ks * 16 + 2 * c;
            qreg[ks][0] = pack2(qp[r0 * D_ + col]     * scale, qp[r0 * D_ + col + 1] * scale);
            qreg[ks][1] = pack2(qp[r1 * D_ + col]     * scale, qp[r1 * D_ + col + 1] * scale);
            qreg[ks][2] = pack2(qp[r0 * D_ + col + 8] * scale, qp[r0 * D_ + col + 9] * scale);
            qreg[ks][3] = pack2(qp[r1 * D_ + col + 8] * scale, qp[r1 * D_ + col + 9] * scale);
        }
    }

    float oacc[16][4];
    #pragma unroll
    for (int nt = 0; nt < 16; ++nt)
        oacc[nt][0] = oacc[nt][1] = oacc[nt][2] = oacc[nt][3] = 0.f;
    float m0 = -1e30f, m1 = -1e30f, l0 = 0.f, l1 = 0.f;

    for (int j = 0; j < njt; ++j) {
        const int st = j & 1;
        if (j + 1 < njt) {
            const int ns = (j + 1) & 1;
            load_kv_tile(kg + (long)(j + 1) * BC * D_,
                         vtg + (j + 1) * BC,     // VT: advance along s (columns)
                         k_u32 + (uint32_t)(ns * KTILE_W) * 4u,
                         v_u32 + (uint32_t)(ns * VTILE_W) * 4u, tid);
            asm volatile("cp.async.wait_group 1;");
        } else {
            asm volatile("cp.async.wait_group 0;");
        }
        __syncthreads();

        const int kvb = j * BC;
        const uint32_t ktb = k_u32 + (uint32_t)(st * KTILE_W) * 4u + koff;
        const uint32_t vtb = v_u32 + (uint32_t)(st * VTILE_W) * 4u + voff;

        // ---- S = Q K^T  (16x64 per warp, 8x8 mmas) ----
        float sacc[8][4];
        #pragma unroll
        for (int nt = 0; nt < 8; ++nt)
            sacc[nt][0] = sacc[nt][1] = sacc[nt][2] = sacc[nt][3] = 0.f;

        #pragma unroll
        for (int nt = 0; nt < 8; ++nt) {
            const uint32_t krow = ktb + (uint32_t)(nt * 8 * KSTW) * 4u;
            #pragma unroll
            for (int kp = 0; kp < 4; ++kp) {
                uint32_t b0, b1, b2, b3;
                ldsm4(b0, b1, b2, b3, krow + (uint32_t)(kp * 16) * 4u);
                mma_f16(sacc[nt], qreg[2*kp][0], qreg[2*kp][1], qreg[2*kp][2], qreg[2*kp][3], b0, b1);
                mma_f16(sacc[nt], qreg[2*kp+1][0], qreg[2*kp+1][1], qreg[2*kp+1][2], qreg[2*kp+1][3], b2, b3);
            }
        }

        // ---- causal mask (near-diagonal tiles only) ----
        if (kvb + BC - 1 > wrow) {
            #pragma unroll
            for (int nt = 0; nt < 8; ++nt) {
                #pragma unroll
                for (int idx = 0; idx < 4; ++idx) {
                    int col = kvb + nt * 8 + (c << 1) + (idx & 1);
                    int row = wrow + g + ((idx >> 1) << 3);
                    if (col > row) sacc[nt][idx] = -1e30f;
                }
            }
        }

        // ---- online softmax (rows g and g+8) ----
        float tm0 = -1e30f, tm1 = -1e30f;
        #pragma unroll
        for (int nt = 0; nt < 8; ++nt) {
            tm0 = fmaxf(tm0, fmaxf(sacc[nt][0], sacc[nt][1]));
            tm1 = fmaxf(tm1, fmaxf(sacc[nt][2], sacc[nt][3]));
        }
        tm0 = fmaxf(tm0, __shfl_xor_sync(0xffffffffu, tm0, 1));
        tm0 = fmaxf(tm0, __shfl_xor_sync(0xffffffffu, tm0, 2));
        tm1 = fmaxf(tm1, __shfl_xor_sync(0xffffffffu, tm1, 1));
        tm1 = fmaxf(tm1, __shfl_xor_sync(0xffffffffu, tm1, 2));

        const float nm0 = fmaxf(m0, tm0), nm1 = fmaxf(m1, tm1);
        const float a0 = __expf(m0 - nm0), a1 = __expf(m1 - nm1);
        m0 = nm0; m1 = nm1;

        float ts0 = 0.f, ts1 = 0.f;
        uint32_t* prow0 = psm + (w * 16 + g) * PSTW;
        uint32_t* prow1 = prow0 + 8 * PSTW;
        #pragma unroll
        for (int nt = 0; nt < 8; ++nt) {
            float p00 = __expf(sacc[nt][0] - nm0);
            float p01 = __expf(sacc[nt][1] - nm0);
            float p10 = __expf(sacc[nt][2] - nm1);
            float p11 = __expf(sacc[nt][3] - nm1);
            ts0 += p00 + p01;
            ts1 += p10 + p11;
            prow0[nt * 4 + c] = pack2(p00, p01);
            prow1[nt * 4 + c] = pack2(p10, p11);
        }
        ts0 += __shfl_xor_sync(0xffffffffu, ts0, 1);
        ts0 += __shfl_xor_sync(0xffffffffu, ts0, 2);
        ts1 += __shfl_xor_sync(0xffffffffu, ts1, 1);
        ts1 += __shfl_xor_sync(0xffffffffu, ts1, 2);
        l0 = l0 * a0 + ts0;
        l1 = l1 * a1 + ts1;

        #pragma unroll
        for (int nt = 0; nt < 16; ++nt) {
            oacc[nt][0] *= a0; oacc[nt][1] *= a0;
            oacc[nt][2] *= a1; oacc[nt][3] *= a1;
        }

        __syncwarp();   // P rows are warp-private; order STS before ldmatrix

        // ---- O += P V  (16x128 per warp, 4x16 mmas) ----
        uint32_t pa[4][4];
        #pragma unroll
        for (int ks = 0; ks < 4; ++ks)
            ldsm4(pa[ks][0], pa[ks][1], pa[ks][2], pa[ks][3],
                  p_u32 + poff + (uint32_t)(ks * 8) * 4u);

        #pragma unroll
        for (int nt = 0; nt < 16; ++nt) {
            const uint32_t vrow = vtb + (uint32_t)(nt * 8 * VSTW) * 4u;
            uint32_t b0, b1, b2, b3, b4, b5, b6, b7;
            ldsm4(b0, b1, b2, b3, vrow);
            ldsm4(b4, b5, b6, b7, vrow + 16u * 4u);
            mma_f16(oacc[nt], pa[0][0], pa[0][1], pa[0][2], pa[0][3], b0, b1);
            mma_f16(oacc[nt], pa[1][0], pa[1][1], pa[1][2], pa[1][3], b2, b3);
            mma_f16(oacc[nt], pa[2][0], pa[2][1], pa[2][2], pa[2][3], b4, b5);
            mma_f16(oacc[nt], pa[3][0], pa[3][1], pa[3][2], pa[3][3], b6, b7);
        }

        __syncthreads();  // all warps done with this stage before refill
    }

    // ---- epilogue: normalize and store ----
    const float inv0 = 1.f / l0, inv1 = 1.f / l1;
    float* op = out + base;
    const long r0 = wrow + g, r1 = r0 + 8;
    #pragma unroll
    for (int nt = 0; nt < 16; ++nt) {
        int col = nt * 8 + (c << 1);
        float2 o0 = make_float2(oacc[nt][0] * inv0, oacc[nt][1] * inv0);
        float2 o1 = make_float2(oacc[nt][2] * inv1, oacc[nt][3] * inv1);
        *(float2*)(op + r0 * D_ + col) = o0;
        *(float2*)(op + r1 * D_ + col) = o1;
    }
}

extern "C" void kernel_launch(void* const* d_in, const int* in_sizes, int n_in,
                              void* d_out, int out_size) {
    const float* q = (const float*)d_in[0];
    const float* k = (const float*)d_in[1];
    const float* v = (const float*)d_in[2];
    float* out = (float*)d_out;

    dim3 pgrid(S_ / 64, D_ / 64, B_ * H_);
    prep_kv_kernel<<<pgrid, 256>>>(v, (const float4*)k);

    cudaFuncSetAttribute(fa_causal_f16_kernel,
                         cudaFuncAttributeMaxDynamicSharedMemorySize, SMEM_BYTES);
    dim3 grid(S_ / BR, B_ * H_);
    fa_causal_f16_kernel<<<grid, THREADS, SMEM_BYTES>>>(q, out);
}